// round 1
// baseline (speedup 1.0000x reference)
#include <cuda_runtime.h>

// Problem constants
#define Bn  4
#define Sn  2048
#define Dn  1024
#define Hn  16
#define DPn 64
#define Mn  (Bn*Sn)          // 8192 rows for projection GEMMs

// Scratch (device globals: allocation-free rule)
__device__ float g_q[Bn*Hn*Sn*DPn];        // [B,H,S,64]
__device__ float g_k[Bn*Hn*Sn*DPn];
__device__ float g_v[Bn*Hn*Sn*DPn];
__device__ float g_concat[Bn*Sn*Dn];       // [B,S,D] head-concat of attn@V
__device__ float g_out_fallback[Bn*Sn*Dn]; // used only if harness wants attn-only

// ---------------------------------------------------------------------------
// SGEMM: C[M,N] = X[M,K] @ W[K,N] + bias[N], M=8192, N=K=1024.
// BM=BN=128, BK=16, 256 threads, 8x8 micro-tile per thread.
// SPLIT=true scatters output into head-split [B,H,S,64] layout.
// ---------------------------------------------------------------------------
template<bool SPLIT>
__global__ void __launch_bounds__(256) gemm_bias_kernel(
    const float* __restrict__ X, const float* __restrict__ W,
    const float* __restrict__ bias, float* __restrict__ out)
{
    const int BM = 128, BN = 128, BK = 16;
    __shared__ float As[BK][BM];   // transposed A tile
    __shared__ float Bs[BK][BN];

    int tid = threadIdx.x;
    int bn = blockIdx.x * BN;
    int bm = blockIdx.y * BM;
    int ty = tid >> 4;     // 0..15
    int tx = tid & 15;     // 0..15

    float acc[8][8];
    #pragma unroll
    for (int i = 0; i < 8; i++)
        #pragma unroll
        for (int j = 0; j < 8; j++) acc[i][j] = 0.f;

    for (int k0 = 0; k0 < Dn; k0 += BK) {
        // Load A tile (128 x 16), stored transposed
        #pragma unroll
        for (int i = 0; i < 2; i++) {
            int idx = tid + i * 256;            // 0..511 float4s
            int row = idx >> 2;                 // 0..127
            int c4  = (idx & 3) << 2;           // 0,4,8,12
            float4 va = *(const float4*)&X[(size_t)(bm + row) * Dn + k0 + c4];
            As[c4 + 0][row] = va.x;
            As[c4 + 1][row] = va.y;
            As[c4 + 2][row] = va.z;
            As[c4 + 3][row] = va.w;
        }
        // Load B tile (16 x 128)
        #pragma unroll
        for (int i = 0; i < 2; i++) {
            int idx = tid + i * 256;
            int r  = idx >> 5;                  // 0..15
            int c4 = (idx & 31) << 2;           // 0..124
            *(float4*)&Bs[r][c4] = *(const float4*)&W[(size_t)(k0 + r) * Dn + bn + c4];
        }
        __syncthreads();

        #pragma unroll
        for (int kk = 0; kk < BK; kk++) {
            float a[8], bb[8];
            *(float4*)&a[0]  = *(const float4*)&As[kk][ty * 8];
            *(float4*)&a[4]  = *(const float4*)&As[kk][ty * 8 + 4];
            *(float4*)&bb[0] = *(const float4*)&Bs[kk][tx * 8];
            *(float4*)&bb[4] = *(const float4*)&Bs[kk][tx * 8 + 4];
            #pragma unroll
            for (int i = 0; i < 8; i++)
                #pragma unroll
                for (int j = 0; j < 8; j++)
                    acc[i][j] += a[i] * bb[j];
        }
        __syncthreads();
    }

    #pragma unroll
    for (int i = 0; i < 8; i++) {
        int m = bm + ty * 8 + i;
        #pragma unroll
        for (int j = 0; j < 8; j++) {
            int n = bn + tx * 8 + j;
            float v = acc[i][j] + bias[n];
            if (SPLIT) {
                int h = n >> 6, d = n & 63;
                int b = m >> 11, s = m & (Sn - 1);
                g_q[0]; // keep compiler honest about global usage (no-op)
                out[(((size_t)(b * Hn + h)) * Sn + s) * DPn + d] = v;
            } else {
                out[(size_t)m * Dn + n] = v;
            }
        }
    }
}

// ---------------------------------------------------------------------------
// Fused attention: one block = (b, h, 16 query rows).
// Full 16x2048 score row-block lives in SMEM -> mask+scale -> softmax ->
// optional attn write -> attn @ V -> concat layout.
// ---------------------------------------------------------------------------
#define QT 16
#define KT 128
#define KST 67   // K/V tile row stride (padding for conflict-free strided reads)

__global__ void __launch_bounds__(256) attn_kernel(
    const float* __restrict__ Mask, float* __restrict__ attn_out, int write_attn)
{
    extern __shared__ float sm[];
    float* sQ = sm;                    // QT*64      = 1024 floats
    float* sS = sm + QT * DPn;         // QT*2048    = 32768 floats
    float* sK = sS + QT * Sn;          // KT*KST     = 8576 floats

    int tid = threadIdx.x;
    int q0 = blockIdx.x * QT;
    int h  = blockIdx.y;
    int b  = blockIdx.z;
    size_t head_base = ((size_t)(b * Hn + h)) * Sn * DPn;

    // Load Q rows (16 x 64)
    {
        int r  = tid >> 4;
        int d4 = (tid & 15) << 2;
        *(float4*)&sQ[r * DPn + d4] =
            *(const float4*)&g_q[head_base + (size_t)(q0 + r) * DPn + d4];
    }
    __syncthreads();

    const float scale = 0.125f;   // 1/sqrt(64)
    int jc = tid & 31;            // 0..31
    int rg = tid >> 5;            // 0..7 (rows rg and rg+8)

    // ---- scores = Q @ K^T * scale + mask * -1e9 ----
    for (int kt = 0; kt < Sn / KT; kt++) {
        int j0 = kt * KT;
        #pragma unroll
        for (int i = 0; i < 8; i++) {
            int idx = tid + i * 256;            // 0..2047 float4s
            int j  = idx >> 4;
            int d4 = (idx & 15) << 2;
            float4 vk = *(const float4*)&g_k[head_base + (size_t)(j0 + j) * DPn + d4];
            sK[j * KST + d4 + 0] = vk.x;
            sK[j * KST + d4 + 1] = vk.y;
            sK[j * KST + d4 + 2] = vk.z;
            sK[j * KST + d4 + 3] = vk.w;
        }
        __syncthreads();

        float acc[2][4];
        #pragma unroll
        for (int rr = 0; rr < 2; rr++)
            #pragma unroll
            for (int c = 0; c < 4; c++) acc[rr][c] = 0.f;

        #pragma unroll 4
        for (int d = 0; d < DPn; d++) {
            float q0v = sQ[rg * DPn + d];
            float q1v = sQ[(rg + 8) * DPn + d];
            #pragma unroll
            for (int c = 0; c < 4; c++) {
                float kv = sK[(jc + 32 * c) * KST + d];
                acc[0][c] += q0v * kv;
                acc[1][c] += q1v * kv;
            }
        }

        #pragma unroll
        for (int rr = 0; rr < 2; rr++) {
            int r = rg + rr * 8;
            size_t mrow = ((size_t)b * Sn + (q0 + r)) * Sn + j0;
            #pragma unroll
            for (int c = 0; c < 4; c++) {
                int col = jc + 32 * c;
                float mval = Mask[mrow + col];
                sS[r * Sn + j0 + col] = acc[rr][c] * scale + mval * (-1e9f);
            }
        }
        __syncthreads();
    }

    // ---- softmax per row (2 rows per warp) ----
    {
        int w = tid >> 5, lane = tid & 31;
        #pragma unroll
        for (int rr = 0; rr < 2; rr++) {
            int r = w * 2 + rr;
            float* row = &sS[r * Sn];
            float mx = -3.4e38f;
            for (int jj = lane; jj < Sn; jj += 32) mx = fmaxf(mx, row[jj]);
            #pragma unroll
            for (int o = 16; o; o >>= 1) mx = fmaxf(mx, __shfl_xor_sync(0xffffffffu, mx, o));
            float sum = 0.f;
            for (int jj = lane; jj < Sn; jj += 32) {
                float e = __expf(row[jj] - mx);
                row[jj] = e;
                sum += e;
            }
            #pragma unroll
            for (int o = 16; o; o >>= 1) sum += __shfl_xor_sync(0xffffffffu, sum, o);
            float inv = 1.f / sum;
            if (write_attn) {
                size_t abase = (((size_t)(b * Hn + h)) * Sn + (q0 + r)) * Sn;
                for (int jj = lane; jj < Sn; jj += 32) {
                    float p = row[jj] * inv;
                    row[jj] = p;
                    attn_out[abase + jj] = p;
                }
            } else {
                for (int jj = lane; jj < Sn; jj += 32) row[jj] *= inv;
            }
        }
    }
    __syncthreads();

    // ---- rep = attn @ V  (16 x 64 output) ----
    int r2 = tid >> 4;            // 0..15
    int dg = (tid & 15) << 2;     // 0,4,...,60
    float acc2[4] = {0.f, 0.f, 0.f, 0.f};

    for (int kt = 0; kt < Sn / KT; kt++) {
        int j0 = kt * KT;
        #pragma unroll
        for (int i = 0; i < 8; i++) {
            int idx = tid + i * 256;
            int j  = idx >> 4;
            int d4 = (idx & 15) << 2;
            float4 vv = *(const float4*)&g_v[head_base + (size_t)(j0 + j) * DPn + d4];
            sK[j * KST + d4 + 0] = vv.x;
            sK[j * KST + d4 + 1] = vv.y;
            sK[j * KST + d4 + 2] = vv.z;
            sK[j * KST + d4 + 3] = vv.w;
        }
        __syncthreads();

        #pragma unroll 4
        for (int j = 0; j < KT; j++) {
            float p = sS[r2 * Sn + j0 + j];
            #pragma unroll
            for (int c = 0; c < 4; c++)
                acc2[c] += p * sK[j * KST + dg + c];
        }
        __syncthreads();
    }

    size_t cbase = ((size_t)b * Sn + (q0 + r2)) * Dn + h * DPn + dg;
    *(float4*)&g_concat[cbase] = make_float4(acc2[0], acc2[1], acc2[2], acc2[3]);
}

// ---------------------------------------------------------------------------
// Launch
// ---------------------------------------------------------------------------
extern "C" void kernel_launch(void* const* d_in, const int* in_sizes, int n_in,
                              void* d_out, int out_size)
{
    const float* Q    = (const float*)d_in[0];
    const float* K    = (const float*)d_in[1];
    const float* V    = (const float*)d_in[2];
    const float* Mask = (const float*)d_in[3];
    const float* Wq   = (const float*)d_in[4];
    const float* bq   = (const float*)d_in[5];
    const float* Wk   = (const float*)d_in[6];
    const float* bk   = (const float*)d_in[7];
    const float* Wv   = (const float*)d_in[8];
    const float* bv   = (const float*)d_in[9];
    const float* Wo   = (const float*)d_in[10];
    const float* bo   = (const float*)d_in[11];

    float *qp, *kp, *vp, *cp, *fb;
    cudaGetSymbolAddress((void**)&qp, g_q);
    cudaGetSymbolAddress((void**)&kp, g_k);
    cudaGetSymbolAddress((void**)&vp, g_v);
    cudaGetSymbolAddress((void**)&cp, g_concat);
    cudaGetSymbolAddress((void**)&fb, g_out_fallback);

    const long long OUT_N  = (long long)Bn * Sn * Dn;        // 8,388,608
    const long long ATTN_N = (long long)Bn * Hn * Sn * Sn;   // 268,435,456
    float* outp  = (float*)d_out;
    float* attnp = nullptr;
    long long osz = (long long)out_size;
    if (osz >= OUT_N + ATTN_N) {
        attnp = (float*)d_out + OUT_N;       // (out, attn) concatenated
    } else if (osz == ATTN_N) {
        attnp = (float*)d_out;               // attn-only output
        outp  = fb;
    } // else: out-only; attnp stays null and attn write is skipped

    dim3 ggrid(Dn / 128, Mn / 128);          // (8, 64)
    gemm_bias_kernel<true><<<ggrid, 256>>>(Q, Wq, bq, qp);
    gemm_bias_kernel<true><<<ggrid, 256>>>(K, Wk, bk, kp);
    gemm_bias_kernel<true><<<ggrid, 256>>>(V, Wv, bv, vp);

    size_t shmem = (size_t)(QT * DPn + QT * Sn + KT * KST) * sizeof(float); // ~169.5 KB
    cudaFuncSetAttribute(attn_kernel, cudaFuncAttributeMaxDynamicSharedMemorySize, (int)shmem);
    attn_kernel<<<dim3(Sn / QT, Hn, Bn), 256, shmem>>>(Mask, attnp, attnp != nullptr);

    gemm_bias_kernel<false><<<ggrid, 256>>>(cp, Wo, bo, outp);
}

// round 3
// speedup vs baseline: 1.7777x; 1.7777x over previous
#include <cuda_runtime.h>
#include <mma.h>
using namespace nvcuda;

// Problem constants
#define Bn  4
#define Sn  2048
#define Dn  1024
#define Hn  16
#define DPn 64
#define Mn  (Bn*Sn)

// Scratch (device globals: allocation-free rule)
__device__ float g_q[Bn*Hn*Sn*DPn];
__device__ float g_k[Bn*Hn*Sn*DPn];
__device__ float g_v[Bn*Hn*Sn*DPn];
__device__ float g_concat[Bn*Sn*Dn];
__device__ float g_out_fallback[Bn*Sn*Dn];

// ---------------------------------------------------------------------------
// tf32 WMMA GEMM: C[M,N] = X[M,K] @ W[K,N] + bias, M=8192, N=K=1024.
// BM=BN=128, BK=16, 256 threads (8 warps), warp tile 32x64 (2x4 frags).
// SPLIT=true scatters into head-split [B,H,S,64].
// ---------------------------------------------------------------------------
template<bool SPLIT>
__global__ void __launch_bounds__(256) gemm_tf32(
    const float* __restrict__ X, const float* __restrict__ W,
    const float* __restrict__ bias, float* __restrict__ out)
{
    __shared__ float As[128][24];      // [m][k], tf32-rounded
    __shared__ float Bs[16][136];      // [k][n], tf32-rounded
    __shared__ float Cs[8][16][16];    // per-warp epilogue patch

    int tid = threadIdx.x;
    int w = tid >> 5, lane = tid & 31;
    int bm = blockIdx.y * 128, bn = blockIdx.x * 128;
    int wm = (w >> 1) * 32;            // warp m offset within tile
    int wn = (w & 1) * 64;             // warp n offset within tile

    wmma::fragment<wmma::accumulator, 16, 16, 8, float> acc[2][4];
    #pragma unroll
    for (int mt = 0; mt < 2; mt++)
        #pragma unroll
        for (int nt = 0; nt < 4; nt++) wmma::fill_fragment(acc[mt][nt], 0.f);

    for (int k0 = 0; k0 < Dn; k0 += 16) {
        // A tile: 128x16 (512 float4 loads)
        #pragma unroll
        for (int i = 0; i < 2; i++) {
            int idx = tid + i * 256;
            int row = idx >> 2, c4 = (idx & 3) << 2;
            float4 v = *(const float4*)&X[(size_t)(bm + row) * Dn + k0 + c4];
            As[row][c4 + 0] = wmma::__float_to_tf32(v.x);
            As[row][c4 + 1] = wmma::__float_to_tf32(v.y);
            As[row][c4 + 2] = wmma::__float_to_tf32(v.z);
            As[row][c4 + 3] = wmma::__float_to_tf32(v.w);
        }
        // B tile: 16x128
        #pragma unroll
        for (int i = 0; i < 2; i++) {
            int idx = tid + i * 256;
            int r = idx >> 5, c4 = (idx & 31) << 2;
            float4 v = *(const float4*)&W[(size_t)(k0 + r) * Dn + bn + c4];
            Bs[r][c4 + 0] = wmma::__float_to_tf32(v.x);
            Bs[r][c4 + 1] = wmma::__float_to_tf32(v.y);
            Bs[r][c4 + 2] = wmma::__float_to_tf32(v.z);
            Bs[r][c4 + 3] = wmma::__float_to_tf32(v.w);
        }
        __syncthreads();

        #pragma unroll
        for (int kk = 0; kk < 16; kk += 8) {
            wmma::fragment<wmma::matrix_a, 16, 16, 8, wmma::precision::tf32, wmma::row_major> af[2];
            wmma::fragment<wmma::matrix_b, 16, 16, 8, wmma::precision::tf32, wmma::row_major> bf[4];
            #pragma unroll
            for (int mt = 0; mt < 2; mt++)
                wmma::load_matrix_sync(af[mt], &As[wm + mt * 16][kk], 24);
            #pragma unroll
            for (int nt = 0; nt < 4; nt++)
                wmma::load_matrix_sync(bf[nt], &Bs[kk][wn + nt * 16], 136);
            #pragma unroll
            for (int mt = 0; mt < 2; mt++)
                #pragma unroll
                for (int nt = 0; nt < 4; nt++)
                    wmma::mma_sync(acc[mt][nt], af[mt], bf[nt], acc[mt][nt]);
        }
        __syncthreads();
    }

    // Epilogue: per-warp patch -> bias add -> (optional) head-split store
    #pragma unroll
    for (int mt = 0; mt < 2; mt++) {
        #pragma unroll
        for (int nt = 0; nt < 4; nt++) {
            wmma::store_matrix_sync(&Cs[w][0][0], acc[mt][nt], 16, wmma::mem_row_major);
            __syncwarp();
            int r = lane >> 1;
            int c = (lane & 1) * 8;
            int m = bm + wm + mt * 16 + r;
            int n0 = bn + wn + nt * 16 + c;
            #pragma unroll
            for (int jj = 0; jj < 8; jj += 4) {
                float4 v = *(float4*)&Cs[w][r][c + jj];
                float4 bb = *(const float4*)&bias[n0 + jj];
                v.x += bb.x; v.y += bb.y; v.z += bb.z; v.w += bb.w;
                if (SPLIT) {
                    int n = n0 + jj;
                    int h = n >> 6, d = n & 63;
                    int b = m >> 11, s = m & (Sn - 1);
                    *(float4*)&out[(((size_t)(b * Hn + h)) * Sn + s) * DPn + d] = v;
                } else {
                    *(float4*)&out[(size_t)m * Dn + n0 + jj] = v;
                }
            }
            __syncwarp();
        }
    }
}

// ---------------------------------------------------------------------------
// Fused attention, WMMA tf32.
// Block = (b, h, 16 q-rows). Full 16x2048 score block in smem.
// Phase 1: QK^T via wmma (Q pre-scaled+tf32 in smem; K frags straight from gmem)
// Phase 2: mask + softmax (exact fp32), write attn, store P tf32 in smem
// Phase 3: P @ V via wmma (V frags straight from gmem), split-k across warps
// ---------------------------------------------------------------------------
#define SLD 2056   // padded score row stride

__global__ void __launch_bounds__(256) attn_tf32(
    const float* __restrict__ Mask, float* __restrict__ attn_out, int write_attn)
{
    extern __shared__ float sm[];
    float* sQ  = sm;                   // 16 x 72
    float* sS  = sm + 16 * 72;         // 16 x 2056
    float* red = sS + 16 * SLD;        // 2 x 16 x 64

    int tid = threadIdx.x, w = tid >> 5, lane = tid & 31;
    int q0 = blockIdx.x * 16;
    int h = blockIdx.y, b = blockIdx.z;
    size_t hb = ((size_t)(b * Hn + h)) * Sn * DPn;

    // Load Q (16x64), fold in scale 1/8, round to tf32
    {
        int r = tid >> 4, c4 = (tid & 15) << 2;
        float4 v = *(const float4*)&g_q[hb + (size_t)(q0 + r) * DPn + c4];
        sQ[r * 72 + c4 + 0] = wmma::__float_to_tf32(v.x * 0.125f);
        sQ[r * 72 + c4 + 1] = wmma::__float_to_tf32(v.y * 0.125f);
        sQ[r * 72 + c4 + 2] = wmma::__float_to_tf32(v.z * 0.125f);
        sQ[r * 72 + c4 + 3] = wmma::__float_to_tf32(v.w * 0.125f);
    }
    __syncthreads();

    // Q fragments (kept in registers for the whole phase 1)
    wmma::fragment<wmma::matrix_a, 16, 16, 8, wmma::precision::tf32, wmma::row_major> aq[8];
    #pragma unroll
    for (int kk = 0; kk < 8; kk++)
        wmma::load_matrix_sync(aq[kk], &sQ[kk * 8], 72);

    // ---- Phase 1: scores ----
    for (int t = 0; t < 16; t++) {
        int j0 = w * 16 + t * 128;
        wmma::fragment<wmma::accumulator, 16, 16, 8, float> acc;
        wmma::fill_fragment(acc, 0.f);
        const float* kbase = &g_k[hb + (size_t)j0 * DPn];
        #pragma unroll
        for (int kk = 0; kk < 8; kk++) {
            wmma::fragment<wmma::matrix_b, 16, 16, 8, wmma::precision::tf32, wmma::col_major> bk;
            wmma::load_matrix_sync(bk, kbase + kk * 8, DPn);
            #pragma unroll
            for (int i = 0; i < bk.num_elements; i++)
                bk.x[i] = wmma::__float_to_tf32(bk.x[i]);
            wmma::mma_sync(acc, aq[kk], bk, acc);
        }
        wmma::store_matrix_sync(&sS[j0], acc, SLD, wmma::mem_row_major);
    }
    __syncthreads();

    // ---- Phase 2: mask + softmax (2 rows per warp) ----
    #pragma unroll
    for (int rr = 0; rr < 2; rr++) {
        int r = w * 2 + rr;
        float* row = &sS[r * SLD];
        const float* mrow = &Mask[((size_t)b * Sn + (q0 + r)) * Sn];
        float mx = -3.4e38f;
        for (int jj = lane; jj < Sn; jj += 32) {
            float sv = row[jj] + mrow[jj] * (-1e9f);
            row[jj] = sv;
            mx = fmaxf(mx, sv);
        }
        #pragma unroll
        for (int o = 16; o; o >>= 1) mx = fmaxf(mx, __shfl_xor_sync(0xffffffffu, mx, o));
        float sum = 0.f;
        for (int jj = lane; jj < Sn; jj += 32) {
            float e = __expf(row[jj] - mx);
            row[jj] = e;
            sum += e;
        }
        #pragma unroll
        for (int o = 16; o; o >>= 1) sum += __shfl_xor_sync(0xffffffffu, sum, o);
        float inv = 1.f / sum;
        if (write_attn) {
            size_t abase = (((size_t)(b * Hn + h)) * Sn + (q0 + r)) * Sn;
            for (int jj = lane; jj < Sn; jj += 32) {
                float p = row[jj] * inv;
                attn_out[abase + jj] = p;
                row[jj] = wmma::__float_to_tf32(p);
            }
        } else {
            for (int jj = lane; jj < Sn; jj += 32)
                row[jj] = wmma::__float_to_tf32(row[jj] * inv);
        }
    }
    __syncthreads();

    // ---- Phase 3: rep = P @ V, split-k (2 halves) x 4 n-tiles across 8 warps ----
    int nt = w & 3, kh = w >> 2;
    wmma::fragment<wmma::accumulator, 16, 16, 8, float> acc2;
    wmma::fill_fragment(acc2, 0.f);
    for (int t = 0; t < 128; t++) {
        int jk = kh * 1024 + t * 8;
        wmma::fragment<wmma::matrix_a, 16, 16, 8, wmma::precision::tf32, wmma::row_major> ap;
        wmma::fragment<wmma::matrix_b, 16, 16, 8, wmma::precision::tf32, wmma::row_major> bv;
        wmma::load_matrix_sync(ap, &sS[jk], SLD);
        wmma::load_matrix_sync(bv, &g_v[hb + (size_t)jk * DPn + nt * 16], DPn);
        #pragma unroll
        for (int i = 0; i < bv.num_elements; i++)
            bv.x[i] = wmma::__float_to_tf32(bv.x[i]);
        wmma::mma_sync(acc2, ap, bv, acc2);
    }
    wmma::store_matrix_sync(&red[kh * 1024 + nt * 16], acc2, 64, wmma::mem_row_major);
    __syncthreads();

    // combine halves, write concat layout
    {
        int r = tid >> 4, c4 = (tid & 15) << 2;
        float4 v0 = *(float4*)&red[r * 64 + c4];
        float4 v1 = *(float4*)&red[1024 + r * 64 + c4];
        float4 o = make_float4(v0.x + v1.x, v0.y + v1.y, v0.z + v1.z, v0.w + v1.w);
        size_t cb = ((size_t)b * Sn + (q0 + r)) * Dn + h * DPn + c4;
        *(float4*)&g_concat[cb] = o;
    }
}

// ---------------------------------------------------------------------------
// Launch
// ---------------------------------------------------------------------------
extern "C" void kernel_launch(void* const* d_in, const int* in_sizes, int n_in,
                              void* d_out, int out_size)
{
    const float* Q    = (const float*)d_in[0];
    const float* K    = (const float*)d_in[1];
    const float* V    = (const float*)d_in[2];
    const float* Mask = (const float*)d_in[3];
    const float* Wq   = (const float*)d_in[4];
    const float* bq   = (const float*)d_in[5];
    const float* Wk   = (const float*)d_in[6];
    const float* bk   = (const float*)d_in[7];
    const float* Wv   = (const float*)d_in[8];
    const float* bv   = (const float*)d_in[9];
    const float* Wo   = (const float*)d_in[10];
    const float* bo   = (const float*)d_in[11];

    float *qp, *kp, *vp, *cp, *fb;
    cudaGetSymbolAddress((void**)&qp, g_q);
    cudaGetSymbolAddress((void**)&kp, g_k);
    cudaGetSymbolAddress((void**)&vp, g_v);
    cudaGetSymbolAddress((void**)&cp, g_concat);
    cudaGetSymbolAddress((void**)&fb, g_out_fallback);

    const long long OUT_N  = (long long)Bn * Sn * Dn;
    const long long ATTN_N = (long long)Bn * Hn * Sn * Sn;
    float* outp  = (float*)d_out;
    float* attnp = nullptr;
    long long osz = (long long)out_size;
    if (osz >= OUT_N + ATTN_N) {
        attnp = (float*)d_out + OUT_N;
    } else if (osz == ATTN_N) {
        attnp = (float*)d_out;
        outp  = fb;
    }

    dim3 ggrid(Dn / 128, Mn / 128);
    gemm_tf32<true><<<ggrid, 256>>>(Q, Wq, bq, qp);
    gemm_tf32<true><<<ggrid, 256>>>(K, Wk, bk, kp);
    gemm_tf32<true><<<ggrid, 256>>>(V, Wv, bv, vp);

    size_t shmem = (size_t)(16 * 72 + 16 * SLD + 2 * 16 * 64) * sizeof(float); // ~144 KB
    cudaFuncSetAttribute(attn_tf32, cudaFuncAttributeMaxDynamicSharedMemorySize, (int)shmem);
    attn_tf32<<<dim3(Sn / 16, Hn, Bn), 256, shmem>>>(Mask, attnp, attnp != nullptr);

    gemm_tf32<false><<<ggrid, 256>>>(cp, Wo, bo, outp);
}

// round 6
// speedup vs baseline: 2.1663x; 1.2186x over previous
#include <cuda_runtime.h>
#include <mma.h>
using namespace nvcuda;

// Problem constants
#define Bn  4
#define Sn  2048
#define Dn  1024
#define Hn  16
#define DPn 64
#define Mn  (Bn*Sn)

// Scratch (device globals: allocation-free rule)
__device__ float g_q[Bn*Hn*Sn*DPn];
__device__ float g_k[Bn*Hn*Sn*DPn];
__device__ float g_v[Bn*Hn*Sn*DPn];
__device__ float g_concat[Bn*Sn*Dn];
__device__ float g_out_fallback[Bn*Sn*Dn];

// ---------------------------------------------------------------------------
// tf32 WMMA GEMM with register-prefetch pipeline.
// C[M,N] = X[M,K] @ W[K,N] + bias. BM=BN=128, BK=16, 256 thr, warp tile 32x64.
// ---------------------------------------------------------------------------
template<bool SPLIT>
__global__ void __launch_bounds__(256) gemm_tf32(
    const float* __restrict__ X, const float* __restrict__ W,
    const float* __restrict__ bias, float* __restrict__ out)
{
    __shared__ float As[128][24];
    __shared__ float Bs[16][136];
    __shared__ float Cs[8][16][16];

    int tid = threadIdx.x;
    int w = tid >> 5, lane = tid & 31;
    int bm = blockIdx.y * 128, bn = blockIdx.x * 128;
    int wm = (w >> 1) * 32;
    int wn = (w & 1) * 64;

    // A-load coords: 2 float4 per thread
    int arow0 = tid >> 2,        ac4 = (tid & 3) << 2;
    int arow1 = (tid + 256) >> 2;
    // B-load coords
    int brow0 = tid >> 5,        bc4 = (tid & 31) << 2;
    int brow1 = (tid + 256) >> 5;

    wmma::fragment<wmma::accumulator, 16, 16, 8, float> acc[2][4];
    #pragma unroll
    for (int mt = 0; mt < 2; mt++)
        #pragma unroll
        for (int nt = 0; nt < 4; nt++) wmma::fill_fragment(acc[mt][nt], 0.f);

    // prefetch tile 0
    float4 pa0 = *(const float4*)&X[(size_t)(bm + arow0) * Dn + ac4];
    float4 pa1 = *(const float4*)&X[(size_t)(bm + arow1) * Dn + ac4];
    float4 pb0 = *(const float4*)&W[(size_t)brow0 * Dn + bn + bc4];
    float4 pb1 = *(const float4*)&W[(size_t)brow1 * Dn + bn + bc4];

    for (int k0 = 0; k0 < Dn; k0 += 16) {
        // commit prefetched tile to smem (tf32-rounded)
        As[arow0][ac4+0] = wmma::__float_to_tf32(pa0.x);
        As[arow0][ac4+1] = wmma::__float_to_tf32(pa0.y);
        As[arow0][ac4+2] = wmma::__float_to_tf32(pa0.z);
        As[arow0][ac4+3] = wmma::__float_to_tf32(pa0.w);
        As[arow1][ac4+0] = wmma::__float_to_tf32(pa1.x);
        As[arow1][ac4+1] = wmma::__float_to_tf32(pa1.y);
        As[arow1][ac4+2] = wmma::__float_to_tf32(pa1.z);
        As[arow1][ac4+3] = wmma::__float_to_tf32(pa1.w);
        Bs[brow0][bc4+0] = wmma::__float_to_tf32(pb0.x);
        Bs[brow0][bc4+1] = wmma::__float_to_tf32(pb0.y);
        Bs[brow0][bc4+2] = wmma::__float_to_tf32(pb0.z);
        Bs[brow0][bc4+3] = wmma::__float_to_tf32(pb0.w);
        Bs[brow1][bc4+0] = wmma::__float_to_tf32(pb1.x);
        Bs[brow1][bc4+1] = wmma::__float_to_tf32(pb1.y);
        Bs[brow1][bc4+2] = wmma::__float_to_tf32(pb1.z);
        Bs[brow1][bc4+3] = wmma::__float_to_tf32(pb1.w);
        __syncthreads();

        // prefetch next tile while computing this one
        if (k0 + 16 < Dn) {
            int kn = k0 + 16;
            pa0 = *(const float4*)&X[(size_t)(bm + arow0) * Dn + kn + ac4];
            pa1 = *(const float4*)&X[(size_t)(bm + arow1) * Dn + kn + ac4];
            pb0 = *(const float4*)&W[(size_t)(kn + brow0) * Dn + bn + bc4];
            pb1 = *(const float4*)&W[(size_t)(kn + brow1) * Dn + bn + bc4];
        }

        #pragma unroll
        for (int kk = 0; kk < 16; kk += 8) {
            wmma::fragment<wmma::matrix_a, 16, 16, 8, wmma::precision::tf32, wmma::row_major> af[2];
            wmma::fragment<wmma::matrix_b, 16, 16, 8, wmma::precision::tf32, wmma::row_major> bf[4];
            #pragma unroll
            for (int mt = 0; mt < 2; mt++)
                wmma::load_matrix_sync(af[mt], &As[wm + mt * 16][kk], 24);
            #pragma unroll
            for (int nt = 0; nt < 4; nt++)
                wmma::load_matrix_sync(bf[nt], &Bs[kk][wn + nt * 16], 136);
            #pragma unroll
            for (int mt = 0; mt < 2; mt++)
                #pragma unroll
                for (int nt = 0; nt < 4; nt++)
                    wmma::mma_sync(acc[mt][nt], af[mt], bf[nt], acc[mt][nt]);
        }
        __syncthreads();
    }

    #pragma unroll
    for (int mt = 0; mt < 2; mt++) {
        #pragma unroll
        for (int nt = 0; nt < 4; nt++) {
            wmma::store_matrix_sync(&Cs[w][0][0], acc[mt][nt], 16, wmma::mem_row_major);
            __syncwarp();
            int r = lane >> 1;
            int c = (lane & 1) * 8;
            int m = bm + wm + mt * 16 + r;
            int n0 = bn + wn + nt * 16 + c;
            #pragma unroll
            for (int jj = 0; jj < 8; jj += 4) {
                float4 v = *(float4*)&Cs[w][r][c + jj];
                float4 bb = *(const float4*)&bias[n0 + jj];
                v.x += bb.x; v.y += bb.y; v.z += bb.z; v.w += bb.w;
                if (SPLIT) {
                    int n = n0 + jj;
                    int h = n >> 6, d = n & 63;
                    int b = m >> 11, s = m & (Sn - 1);
                    *(float4*)&out[(((size_t)(b * Hn + h)) * Sn + s) * DPn + d] = v;
                } else {
                    *(float4*)&out[(size_t)m * Dn + n0 + jj] = v;
                }
            }
            __syncwarp();
        }
    }
}

// ---------------------------------------------------------------------------
// Fused attention, WMMA tf32, smem-staged K/V.
// Block = (b,h,16 q-rows), 512 threads (16 warps).
// smem: sQ 16x72 | sS 16x2056 | sKV 256x72 (reused as 4x16x64 reduction buf)
// ---------------------------------------------------------------------------
#define SLD 2056
#define KTR 256
#define KVLD 72

__global__ void __launch_bounds__(512) attn_tf32(
    const float* __restrict__ Mask, float* __restrict__ attn_out, int write_attn)
{
    extern __shared__ float sm[];
    float* sQ  = sm;                        // 1152
    float* sS  = sm + 16 * KVLD;            // 32896
    float* sKV = sS + 16 * SLD;             // 18432
    float* red = sKV;                       // alias (used after last V tile)

    int tid = threadIdx.x, w = tid >> 5, lane = tid & 31;
    int q0 = blockIdx.x * 16;
    int h = blockIdx.y, b = blockIdx.z;
    size_t hb = ((size_t)(b * Hn + h)) * Sn * DPn;

    // Load Q (16x64), fold scale, tf32
    if (tid < 256) {
        int r = tid >> 4, c4 = (tid & 15) << 2;
        float4 v = *(const float4*)&g_q[hb + (size_t)(q0 + r) * DPn + c4];
        sQ[r * KVLD + c4 + 0] = wmma::__float_to_tf32(v.x * 0.125f);
        sQ[r * KVLD + c4 + 1] = wmma::__float_to_tf32(v.y * 0.125f);
        sQ[r * KVLD + c4 + 2] = wmma::__float_to_tf32(v.z * 0.125f);
        sQ[r * KVLD + c4 + 3] = wmma::__float_to_tf32(v.w * 0.125f);
    }
    __syncthreads();

    wmma::fragment<wmma::matrix_a, 16, 16, 8, wmma::precision::tf32, wmma::row_major> aq[8];
    #pragma unroll
    for (int kk = 0; kk < 8; kk++)
        wmma::load_matrix_sync(aq[kk], &sQ[kk * 8], KVLD);

    int srow = tid >> 4, sc4 = (tid & 15) << 2;   // staging coords (512 thr -> 32 rows/pass)

    // ---- Phase 1: scores = (Q*scale) @ K^T ----
    for (int t = 0; t < Sn / KTR; t++) {
        int j0 = t * KTR;
        #pragma unroll
        for (int i = 0; i < KTR / 32; i++) {
            int row = srow + i * 32;
            float4 v = *(const float4*)&g_k[hb + (size_t)(j0 + row) * DPn + sc4];
            sKV[row * KVLD + sc4 + 0] = wmma::__float_to_tf32(v.x);
            sKV[row * KVLD + sc4 + 1] = wmma::__float_to_tf32(v.y);
            sKV[row * KVLD + sc4 + 2] = wmma::__float_to_tf32(v.z);
            sKV[row * KVLD + sc4 + 3] = wmma::__float_to_tf32(v.w);
        }
        __syncthreads();

        wmma::fragment<wmma::accumulator, 16, 16, 8, float> acc;
        wmma::fill_fragment(acc, 0.f);
        #pragma unroll
        for (int kk = 0; kk < 8; kk++) {
            wmma::fragment<wmma::matrix_b, 16, 16, 8, wmma::precision::tf32, wmma::col_major> bk;
            wmma::load_matrix_sync(bk, &sKV[(w * 16) * KVLD + kk * 8], KVLD);
            wmma::mma_sync(acc, aq[kk], bk, acc);
        }
        wmma::store_matrix_sync(&sS[j0 + w * 16], acc, SLD, wmma::mem_row_major);
        __syncthreads();
    }

    // ---- Phase 2: mask + softmax, one warp per row ----
    {
        int r = w;
        float* row = &sS[r * SLD];
        const float* mrow = &Mask[((size_t)b * Sn + (q0 + r)) * Sn];
        float mx = -3.4e38f;
        for (int jj = lane; jj < Sn; jj += 32) {
            float sv = row[jj] + mrow[jj] * (-1e9f);
            row[jj] = sv;
            mx = fmaxf(mx, sv);
        }
        #pragma unroll
        for (int o = 16; o; o >>= 1) mx = fmaxf(mx, __shfl_xor_sync(0xffffffffu, mx, o));
        float sum = 0.f;
        for (int jj = lane; jj < Sn; jj += 32) {
            float e = __expf(row[jj] - mx);
            row[jj] = e;
            sum += e;
        }
        #pragma unroll
        for (int o = 16; o; o >>= 1) sum += __shfl_xor_sync(0xffffffffu, sum, o);
        float inv = 1.f / sum;
        if (write_attn) {
            size_t abase = (((size_t)(b * Hn + h)) * Sn + (q0 + r)) * Sn;
            for (int jj = lane; jj < Sn; jj += 32) {
                float p = row[jj] * inv;
                attn_out[abase + jj] = p;
                row[jj] = wmma::__float_to_tf32(p);
            }
        } else {
            for (int jj = lane; jj < Sn; jj += 32)
                row[jj] = wmma::__float_to_tf32(row[jj] * inv);
        }
    }
    __syncthreads();

    // ---- Phase 3: rep = P @ V. warp -> (kh = k-quarter, nt = 16-col tile) ----
    int nt = w & 3, kh = w >> 2;
    wmma::fragment<wmma::accumulator, 16, 16, 8, float> acc2;
    wmma::fill_fragment(acc2, 0.f);

    for (int t = 0; t < Sn / KTR; t++) {
        int j0 = t * KTR;
        #pragma unroll
        for (int i = 0; i < KTR / 32; i++) {
            int row = srow + i * 32;
            float4 v = *(const float4*)&g_v[hb + (size_t)(j0 + row) * DPn + sc4];
            sKV[row * KVLD + sc4 + 0] = wmma::__float_to_tf32(v.x);
            sKV[row * KVLD + sc4 + 1] = wmma::__float_to_tf32(v.y);
            sKV[row * KVLD + sc4 + 2] = wmma::__float_to_tf32(v.z);
            sKV[row * KVLD + sc4 + 3] = wmma::__float_to_tf32(v.w);
        }
        __syncthreads();

        #pragma unroll
        for (int f = 0; f < 8; f++) {
            int kl = kh * 64 + f * 8;          // local k row within tile
            wmma::fragment<wmma::matrix_a, 16, 16, 8, wmma::precision::tf32, wmma::row_major> ap;
            wmma::fragment<wmma::matrix_b, 16, 16, 8, wmma::precision::tf32, wmma::row_major> bv;
            wmma::load_matrix_sync(ap, &sS[j0 + kl], SLD);
            wmma::load_matrix_sync(bv, &sKV[kl * KVLD + nt * 16], KVLD);
            wmma::mma_sync(acc2, ap, bv, acc2);
        }
        __syncthreads();
    }

    // reduction across 4 k-quarters (red aliases sKV; all mma done)
    wmma::store_matrix_sync(&red[kh * 1024 + nt * 16], acc2, 64, wmma::mem_row_major);
    __syncthreads();

    for (int idx = tid; idx < 1024; idx += 512) {
        int r = idx >> 6, c = idx & 63;
        float s = red[r * 64 + c] + red[1024 + r * 64 + c]
                + red[2048 + r * 64 + c] + red[3072 + r * 64 + c];
        g_concat[((size_t)b * Sn + (q0 + r)) * Dn + h * DPn + c] = s;
    }
}

// ---------------------------------------------------------------------------
// Launch
// ---------------------------------------------------------------------------
extern "C" void kernel_launch(void* const* d_in, const int* in_sizes, int n_in,
                              void* d_out, int out_size)
{
    const float* Q    = (const float*)d_in[0];
    const float* K    = (const float*)d_in[1];
    const float* V    = (const float*)d_in[2];
    const float* Mask = (const float*)d_in[3];
    const float* Wq   = (const float*)d_in[4];
    const float* bq   = (const float*)d_in[5];
    const float* Wk   = (const float*)d_in[6];
    const float* bk   = (const float*)d_in[7];
    const float* Wv   = (const float*)d_in[8];
    const float* bv   = (const float*)d_in[9];
    const float* Wo   = (const float*)d_in[10];
    const float* bo   = (const float*)d_in[11];

    float *qp, *kp, *vp, *cp, *fb;
    cudaGetSymbolAddress((void**)&qp, g_q);
    cudaGetSymbolAddress((void**)&kp, g_k);
    cudaGetSymbolAddress((void**)&vp, g_v);
    cudaGetSymbolAddress((void**)&cp, g_concat);
    cudaGetSymbolAddress((void**)&fb, g_out_fallback);

    const long long OUT_N  = (long long)Bn * Sn * Dn;
    const long long ATTN_N = (long long)Bn * Hn * Sn * Sn;
    float* outp  = (float*)d_out;
    float* attnp = nullptr;
    long long osz = (long long)out_size;
    if (osz >= OUT_N + ATTN_N) {
        attnp = (float*)d_out + OUT_N;
    } else if (osz == ATTN_N) {
        attnp = (float*)d_out;
        outp  = fb;
    }

    dim3 ggrid(Dn / 128, Mn / 128);
    gemm_tf32<true><<<ggrid, 256>>>(Q, Wq, bq, qp);
    gemm_tf32<true><<<ggrid, 256>>>(K, Wk, bk, kp);
    gemm_tf32<true><<<ggrid, 256>>>(V, Wv, bv, vp);

    size_t shmem = (size_t)(16 * KVLD + 16 * SLD + KTR * KVLD) * sizeof(float); // ~205 KB
    cudaFuncSetAttribute(attn_tf32, cudaFuncAttributeMaxDynamicSharedMemorySize, (int)shmem);
    attn_tf32<<<dim3(Sn / 16, Hn, Bn), 512, shmem>>>(Mask, attnp, attnp != nullptr);

    gemm_tf32<false><<<ggrid, 256>>>(cp, Wo, bo, outp);
}

// round 8
// speedup vs baseline: 2.6269x; 1.2127x over previous
#include <cuda_runtime.h>
#include <mma.h>
using namespace nvcuda;

// Problem constants
#define Bn  4
#define Sn  2048
#define Dn  1024
#define Hn  16
#define DPn 64
#define Mn  (Bn*Sn)

// Scratch (device globals: allocation-free rule)
__device__ float g_q[Bn*Hn*Sn*DPn];
__device__ float g_k[Bn*Hn*Sn*DPn];
__device__ float g_v[Bn*Hn*Sn*DPn];
__device__ float g_concat[Bn*Sn*Dn];
__device__ float g_out_fallback[Bn*Sn*Dn];
__device__ float g_attn_fb[(size_t)Bn*Hn*Sn*Sn];   // used only if attn not in d_out

// ---------------------------------------------------------------------------
// tf32 WMMA GEMM, BK=32, register-prefetch pipeline.
// C[M,N] = X[M,K] @ W[K,N] + bias. BM=BN=128, 256 thr, warp tile 32x64.
// Grid.z selects one of up to 3 independent (X,W,bias,out) problems.
// ---------------------------------------------------------------------------
template<bool SPLIT>
__global__ void __launch_bounds__(256) gemm_tf32(
    const float* __restrict__ X0, const float* __restrict__ W0,
    const float* __restrict__ b0, float* __restrict__ o0,
    const float* __restrict__ X1, const float* __restrict__ W1,
    const float* __restrict__ b1, float* __restrict__ o1,
    const float* __restrict__ X2, const float* __restrict__ W2,
    const float* __restrict__ b2, float* __restrict__ o2)
{
    const float* X = X0; const float* W = W0; const float* bias = b0; float* out = o0;
    if (blockIdx.z == 1) { X = X1; W = W1; bias = b1; out = o1; }
    else if (blockIdx.z == 2) { X = X2; W = W2; bias = b2; out = o2; }

    __shared__ float As[128][40];     // [m][k]
    __shared__ float Bs[32][136];     // [k][n]
    __shared__ float Cs[8][16][16];

    int tid = threadIdx.x;
    int w = tid >> 5, lane = tid & 31;
    int bm = blockIdx.y * 128, bn = blockIdx.x * 128;
    int wm = (w >> 1) * 32;
    int wn = (w & 1) * 64;

    // A: 128x32 = 1024 float4; 4 per thread
    int ar[4], ac4 = (tid & 7) << 2;
    // B: 32x128 = 1024 float4; 4 per thread
    int br[4], bc4 = (tid & 31) << 2;
    #pragma unroll
    for (int i = 0; i < 4; i++) { ar[i] = (tid + i * 256) >> 3; br[i] = (tid + i * 256) >> 5; }

    wmma::fragment<wmma::accumulator, 16, 16, 8, float> acc[2][4];
    #pragma unroll
    for (int mt = 0; mt < 2; mt++)
        #pragma unroll
        for (int nt = 0; nt < 4; nt++) wmma::fill_fragment(acc[mt][nt], 0.f);

    float4 pa[4], pb[4];
    #pragma unroll
    for (int i = 0; i < 4; i++) {
        pa[i] = *(const float4*)&X[(size_t)(bm + ar[i]) * Dn + ac4];
        pb[i] = *(const float4*)&W[(size_t)br[i] * Dn + bn + bc4];
    }

    for (int k0 = 0; k0 < Dn; k0 += 32) {
        #pragma unroll
        for (int i = 0; i < 4; i++) {
            As[ar[i]][ac4+0] = wmma::__float_to_tf32(pa[i].x);
            As[ar[i]][ac4+1] = wmma::__float_to_tf32(pa[i].y);
            As[ar[i]][ac4+2] = wmma::__float_to_tf32(pa[i].z);
            As[ar[i]][ac4+3] = wmma::__float_to_tf32(pa[i].w);
            Bs[br[i]][bc4+0] = wmma::__float_to_tf32(pb[i].x);
            Bs[br[i]][bc4+1] = wmma::__float_to_tf32(pb[i].y);
            Bs[br[i]][bc4+2] = wmma::__float_to_tf32(pb[i].z);
            Bs[br[i]][bc4+3] = wmma::__float_to_tf32(pb[i].w);
        }
        __syncthreads();

        if (k0 + 32 < Dn) {
            int kn = k0 + 32;
            #pragma unroll
            for (int i = 0; i < 4; i++) {
                pa[i] = *(const float4*)&X[(size_t)(bm + ar[i]) * Dn + kn + ac4];
                pb[i] = *(const float4*)&W[(size_t)(kn + br[i]) * Dn + bn + bc4];
            }
        }

        #pragma unroll
        for (int kk = 0; kk < 32; kk += 8) {
            wmma::fragment<wmma::matrix_a, 16, 16, 8, wmma::precision::tf32, wmma::row_major> af[2];
            wmma::fragment<wmma::matrix_b, 16, 16, 8, wmma::precision::tf32, wmma::row_major> bf[4];
            #pragma unroll
            for (int mt = 0; mt < 2; mt++)
                wmma::load_matrix_sync(af[mt], &As[wm + mt * 16][kk], 40);
            #pragma unroll
            for (int nt = 0; nt < 4; nt++)
                wmma::load_matrix_sync(bf[nt], &Bs[kk][wn + nt * 16], 136);
            #pragma unroll
            for (int mt = 0; mt < 2; mt++)
                #pragma unroll
                for (int nt = 0; nt < 4; nt++)
                    wmma::mma_sync(acc[mt][nt], af[mt], bf[nt], acc[mt][nt]);
        }
        __syncthreads();
    }

    #pragma unroll
    for (int mt = 0; mt < 2; mt++) {
        #pragma unroll
        for (int nt = 0; nt < 4; nt++) {
            wmma::store_matrix_sync(&Cs[w][0][0], acc[mt][nt], 16, wmma::mem_row_major);
            __syncwarp();
            int r = lane >> 1;
            int c = (lane & 1) * 8;
            int m = bm + wm + mt * 16 + r;
            int n0 = bn + wn + nt * 16 + c;
            #pragma unroll
            for (int jj = 0; jj < 8; jj += 4) {
                float4 v = *(float4*)&Cs[w][r][c + jj];
                float4 bb = *(const float4*)&bias[n0 + jj];
                v.x += bb.x; v.y += bb.y; v.z += bb.z; v.w += bb.w;
                if (SPLIT) {
                    int n = n0 + jj;
                    int h = n >> 6, d = n & 63;
                    int b = m >> 11, s = m & (Sn - 1);
                    *(float4*)&out[(((size_t)(b * Hn + h)) * Sn + s) * DPn + d] = v;
                } else {
                    *(float4*)&out[(size_t)m * Dn + n0 + jj] = v;
                }
            }
            __syncwarp();
        }
    }
}

// ---------------------------------------------------------------------------
// K1: scores = (Q*scale)@K^T, mask, softmax, write attn.
// Block = (b,h,16 q-rows), 512 threads. K tiles of 256 rows, reg-prefetched.
// ---------------------------------------------------------------------------
#define SLD 2056
#define KTR 256
#define KVLD 72

__global__ void __launch_bounds__(512) attn_scores(
    const float* __restrict__ Mask, float* __restrict__ attn_out)
{
    extern __shared__ float sm[];
    float* sQ  = sm;                   // 16 x 72
    float* sS  = sm + 16 * KVLD;       // 16 x 2056
    float* sKV = sS + 16 * SLD;        // 256 x 72

    int tid = threadIdx.x, w = tid >> 5, lane = tid & 31;
    int q0 = blockIdx.x * 16;
    int h = blockIdx.y, b = blockIdx.z;
    size_t hb = ((size_t)(b * Hn + h)) * Sn * DPn;

    if (tid < 256) {
        int r = tid >> 4, c4 = (tid & 15) << 2;
        float4 v = *(const float4*)&g_q[hb + (size_t)(q0 + r) * DPn + c4];
        sQ[r * KVLD + c4 + 0] = wmma::__float_to_tf32(v.x * 0.125f);
        sQ[r * KVLD + c4 + 1] = wmma::__float_to_tf32(v.y * 0.125f);
        sQ[r * KVLD + c4 + 2] = wmma::__float_to_tf32(v.z * 0.125f);
        sQ[r * KVLD + c4 + 3] = wmma::__float_to_tf32(v.w * 0.125f);
    }
    __syncthreads();

    wmma::fragment<wmma::matrix_a, 16, 16, 8, wmma::precision::tf32, wmma::row_major> aq[8];
    #pragma unroll
    for (int kk = 0; kk < 8; kk++)
        wmma::load_matrix_sync(aq[kk], &sQ[kk * 8], KVLD);

    int srow = tid >> 4, sc4 = (tid & 15) << 2;   // 32 rows per pass, 8 passes

    float4 pf[8];
    #pragma unroll
    for (int i = 0; i < 8; i++)
        pf[i] = *(const float4*)&g_k[hb + (size_t)(srow + i * 32) * DPn + sc4];

    for (int t = 0; t < Sn / KTR; t++) {
        #pragma unroll
        for (int i = 0; i < 8; i++) {
            int row = srow + i * 32;
            sKV[row * KVLD + sc4 + 0] = wmma::__float_to_tf32(pf[i].x);
            sKV[row * KVLD + sc4 + 1] = wmma::__float_to_tf32(pf[i].y);
            sKV[row * KVLD + sc4 + 2] = wmma::__float_to_tf32(pf[i].z);
            sKV[row * KVLD + sc4 + 3] = wmma::__float_to_tf32(pf[i].w);
        }
        __syncthreads();

        if (t + 1 < Sn / KTR) {
            size_t nb = hb + (size_t)(t + 1) * KTR * DPn;
            #pragma unroll
            for (int i = 0; i < 8; i++)
                pf[i] = *(const float4*)&g_k[nb + (size_t)(srow + i * 32) * DPn + sc4];
        }

        wmma::fragment<wmma::accumulator, 16, 16, 8, float> acc;
        wmma::fill_fragment(acc, 0.f);
        #pragma unroll
        for (int kk = 0; kk < 8; kk++) {
            wmma::fragment<wmma::matrix_b, 16, 16, 8, wmma::precision::tf32, wmma::col_major> bk;
            wmma::load_matrix_sync(bk, &sKV[(w * 16) * KVLD + kk * 8], KVLD);
            wmma::mma_sync(acc, aq[kk], bk, acc);
        }
        wmma::store_matrix_sync(&sS[t * KTR + w * 16], acc, SLD, wmma::mem_row_major);
        __syncthreads();
    }

    // softmax: one warp per row, float4 passes
    {
        int r = w;
        float* row = &sS[r * SLD];
        const float* mrow = &Mask[((size_t)b * Sn + (q0 + r)) * Sn];
        float mx = -3.4e38f;
        #pragma unroll 4
        for (int c = 0; c < 16; c++) {
            int jj = lane * 4 + c * 128;
            float4 s4 = *(float4*)&row[jj];
            float4 m4 = *(const float4*)&mrow[jj];
            s4.x += m4.x * (-1e9f); s4.y += m4.y * (-1e9f);
            s4.z += m4.z * (-1e9f); s4.w += m4.w * (-1e9f);
            *(float4*)&row[jj] = s4;
            mx = fmaxf(mx, fmaxf(fmaxf(s4.x, s4.y), fmaxf(s4.z, s4.w)));
        }
        #pragma unroll
        for (int o = 16; o; o >>= 1) mx = fmaxf(mx, __shfl_xor_sync(0xffffffffu, mx, o));
        float sum = 0.f;
        #pragma unroll 4
        for (int c = 0; c < 16; c++) {
            int jj = lane * 4 + c * 128;
            float4 s4 = *(float4*)&row[jj];
            s4.x = __expf(s4.x - mx); s4.y = __expf(s4.y - mx);
            s4.z = __expf(s4.z - mx); s4.w = __expf(s4.w - mx);
            *(float4*)&row[jj] = s4;
            sum += s4.x + s4.y + s4.z + s4.w;
        }
        #pragma unroll
        for (int o = 16; o; o >>= 1) sum += __shfl_xor_sync(0xffffffffu, sum, o);
        float inv = 1.f / sum;
        float* arow = &attn_out[(((size_t)(b * Hn + h)) * Sn + (q0 + r)) * Sn];
        #pragma unroll 4
        for (int c = 0; c < 16; c++) {
            int jj = lane * 4 + c * 128;
            float4 s4 = *(float4*)&row[jj];
            s4.x *= inv; s4.y *= inv; s4.z *= inv; s4.w *= inv;
            *(float4*)&arow[jj] = s4;
        }
    }
}

// ---------------------------------------------------------------------------
// K2: concat[b, s, h*64 + d] = P[b,h,s,:] @ V[b,h,:,d].
// Block = 128 q-rows x 64 cols, 256 thr (8 warps: warp w = rows w*16..w*16+15).
// K loop BK=32, register-prefetch.
// ---------------------------------------------------------------------------
__global__ void __launch_bounds__(256) attn_pv(const float* __restrict__ P)
{
    __shared__ float sP[128][40];
    __shared__ float sV[32][72];

    int tid = threadIdx.x, w = tid >> 5;
    int m0 = blockIdx.x * 128;
    int h = blockIdx.y, b = blockIdx.z;
    const float* Ph = P + ((size_t)(b * Hn + h)) * Sn * Sn;
    const float* Vh = g_v + ((size_t)(b * Hn + h)) * Sn * DPn;

    // P: 128x32 = 1024 f4, 4/thread ; V: 32x64 = 512 f4, 2/thread
    int pr[4], pc4 = (tid & 7) << 2;
    #pragma unroll
    for (int i = 0; i < 4; i++) pr[i] = (tid + i * 256) >> 3;
    int vr0 = tid >> 4, vr1 = (tid + 256) >> 4, vc4 = (tid & 15) << 2;

    wmma::fragment<wmma::accumulator, 16, 16, 8, float> acc[4];
    #pragma unroll
    for (int nt = 0; nt < 4; nt++) wmma::fill_fragment(acc[nt], 0.f);

    float4 pp[4], pv0, pv1;
    #pragma unroll
    for (int i = 0; i < 4; i++)
        pp[i] = *(const float4*)&Ph[(size_t)(m0 + pr[i]) * Sn + pc4];
    pv0 = *(const float4*)&Vh[(size_t)vr0 * DPn + vc4];
    pv1 = *(const float4*)&Vh[(size_t)vr1 * DPn + vc4];

    for (int k0 = 0; k0 < Sn; k0 += 32) {
        #pragma unroll
        for (int i = 0; i < 4; i++) {
            sP[pr[i]][pc4+0] = wmma::__float_to_tf32(pp[i].x);
            sP[pr[i]][pc4+1] = wmma::__float_to_tf32(pp[i].y);
            sP[pr[i]][pc4+2] = wmma::__float_to_tf32(pp[i].z);
            sP[pr[i]][pc4+3] = wmma::__float_to_tf32(pp[i].w);
        }
        sV[vr0][vc4+0] = wmma::__float_to_tf32(pv0.x);
        sV[vr0][vc4+1] = wmma::__float_to_tf32(pv0.y);
        sV[vr0][vc4+2] = wmma::__float_to_tf32(pv0.z);
        sV[vr0][vc4+3] = wmma::__float_to_tf32(pv0.w);
        sV[vr1][vc4+0] = wmma::__float_to_tf32(pv1.x);
        sV[vr1][vc4+1] = wmma::__float_to_tf32(pv1.y);
        sV[vr1][vc4+2] = wmma::__float_to_tf32(pv1.z);
        sV[vr1][vc4+3] = wmma::__float_to_tf32(pv1.w);
        __syncthreads();

        if (k0 + 32 < Sn) {
            int kn = k0 + 32;
            #pragma unroll
            for (int i = 0; i < 4; i++)
                pp[i] = *(const float4*)&Ph[(size_t)(m0 + pr[i]) * Sn + kn + pc4];
            pv0 = *(const float4*)&Vh[(size_t)(kn + vr0) * DPn + vc4];
            pv1 = *(const float4*)&Vh[(size_t)(kn + vr1) * DPn + vc4];
        }

        #pragma unroll
        for (int kk = 0; kk < 32; kk += 8) {
            wmma::fragment<wmma::matrix_a, 16, 16, 8, wmma::precision::tf32, wmma::row_major> ap;
            wmma::load_matrix_sync(ap, &sP[w * 16][kk], 40);
            #pragma unroll
            for (int nt = 0; nt < 4; nt++) {
                wmma::fragment<wmma::matrix_b, 16, 16, 8, wmma::precision::tf32, wmma::row_major> bv;
                wmma::load_matrix_sync(bv, &sV[kk][nt * 16], 72);
                wmma::mma_sync(acc[nt], ap, bv, acc[nt]);
            }
        }
        __syncthreads();
    }

    // store 16x64 per warp straight to gmem (row stride Dn)
    #pragma unroll
    for (int nt = 0; nt < 4; nt++) {
        float* dst = &g_concat[((size_t)b * Sn + (m0 + w * 16)) * Dn + h * DPn + nt * 16];
        wmma::store_matrix_sync(dst, acc[nt], Dn, wmma::mem_row_major);
    }
}

// ---------------------------------------------------------------------------
// Launch
// ---------------------------------------------------------------------------
extern "C" void kernel_launch(void* const* d_in, const int* in_sizes, int n_in,
                              void* d_out, int out_size)
{
    const float* Q    = (const float*)d_in[0];
    const float* K    = (const float*)d_in[1];
    const float* V    = (const float*)d_in[2];
    const float* Mask = (const float*)d_in[3];
    const float* Wq   = (const float*)d_in[4];
    const float* bq   = (const float*)d_in[5];
    const float* Wk   = (const float*)d_in[6];
    const float* bk   = (const float*)d_in[7];
    const float* Wv   = (const float*)d_in[8];
    const float* bv   = (const float*)d_in[9];
    const float* Wo   = (const float*)d_in[10];
    const float* bo   = (const float*)d_in[11];

    float *qp, *kp, *vp, *cp, *fb, *afb;
    cudaGetSymbolAddress((void**)&qp, g_q);
    cudaGetSymbolAddress((void**)&kp, g_k);
    cudaGetSymbolAddress((void**)&vp, g_v);
    cudaGetSymbolAddress((void**)&cp, g_concat);
    cudaGetSymbolAddress((void**)&fb, g_out_fallback);
    cudaGetSymbolAddress((void**)&afb, g_attn_fb);

    const long long OUT_N  = (long long)Bn * Sn * Dn;
    const long long ATTN_N = (long long)Bn * Hn * Sn * Sn;
    float* outp  = (float*)d_out;
    float* attnp = afb;
    long long osz = (long long)out_size;
    if (osz >= OUT_N + ATTN_N) {
        attnp = (float*)d_out + OUT_N;
    } else if (osz == ATTN_N) {
        attnp = (float*)d_out;
        outp  = fb;
    }

    // QKV projections in one launch
    dim3 ggrid(Dn / 128, Mn / 128, 3);
    gemm_tf32<true><<<ggrid, 256>>>(Q, Wq, bq, qp,
                                    K, Wk, bk, kp,
                                    V, Wv, bv, vp);

    size_t shmem = (size_t)(16 * KVLD + 16 * SLD + KTR * KVLD) * sizeof(float); // ~205 KB
    cudaFuncSetAttribute(attn_scores, cudaFuncAttributeMaxDynamicSharedMemorySize, (int)shmem);
    attn_scores<<<dim3(Sn / 16, Hn, Bn), 512, shmem>>>(Mask, attnp);

    attn_pv<<<dim3(Sn / 128, Hn, Bn), 256>>>(attnp);

    dim3 ogrid(Dn / 128, Mn / 128, 1);
    gemm_tf32<false><<<ogrid, 256>>>(cp, Wo, bo, outp,
                                     cp, Wo, bo, outp,
                                     cp, Wo, bo, outp);
}

// round 9
// speedup vs baseline: 2.6640x; 1.0141x over previous
#include <cuda_runtime.h>
#include <mma.h>
using namespace nvcuda;

// Problem constants
#define Bn  4
#define Sn  2048
#define Dn  1024
#define Hn  16
#define DPn 64
#define Mn  (Bn*Sn)

// Scratch (device globals: allocation-free rule)
__device__ float g_q[Bn*Hn*Sn*DPn];
__device__ float g_k[Bn*Hn*Sn*DPn];
__device__ float g_v[Bn*Hn*Sn*DPn];
__device__ float g_concat[Bn*Sn*Dn];
__device__ float g_out_fallback[Bn*Sn*Dn];
__device__ float g_attn_fb[(size_t)Bn*Hn*Sn*Sn];
__device__ float g_rx[3][(size_t)Mn*Dn];      // tf32-rounded Q,K,V inputs
__device__ float g_rw[4][(size_t)Dn*Dn];      // tf32-rounded Wq,Wk,Wv,Wo

// ---------------- cp.async helpers ----------------
__device__ __forceinline__ void cp16(void* smem_dst, const void* gmem_src) {
    unsigned d = (unsigned)__cvta_generic_to_shared(smem_dst);
    asm volatile("cp.async.ca.shared.global [%0], [%1], 16;\n" :: "r"(d), "l"(gmem_src));
}
__device__ __forceinline__ void cp_commit() {
    asm volatile("cp.async.commit_group;\n");
}
__device__ __forceinline__ void cp_wait0() {
    asm volatile("cp.async.wait_group 0;\n");
}

// ---------------------------------------------------------------------------
// Pre-round inputs/weights to tf32 (RN). grid.y picks tensor.
// ---------------------------------------------------------------------------
struct RoundArgs { const float* s[7]; float* d[7]; int n[7]; };

__global__ void __launch_bounds__(256) round_tf32_k(RoundArgs a)
{
    int t = blockIdx.y;
    int i = (blockIdx.x * 256 + threadIdx.x) * 4;
    if (i >= a.n[t]) return;
    float4 v = *(const float4*)&a.s[t][i];
    v.x = wmma::__float_to_tf32(v.x);
    v.y = wmma::__float_to_tf32(v.y);
    v.z = wmma::__float_to_tf32(v.z);
    v.w = wmma::__float_to_tf32(v.w);
    *(float4*)&a.d[t][i] = v;
}

// ---------------------------------------------------------------------------
// tf32 WMMA GEMM, cp.async 2-stage pipeline. Inputs ALREADY tf32-rounded.
// C[M,N] = X[M,K]@W[K,N] + bias. BM=BN=128, BK=32, 256 thr, warp 32x64.
// ROUND_OUT: round result to tf32 (for tensors feeding later GEMMs).
// ---------------------------------------------------------------------------
#define ALD 40
#define BLD 136
#define ASZ (128*ALD)       // 5120 floats per stage
#define BSZ (32*BLD)        // 4352 floats per stage
#define GSM ((2*ASZ + 2*BSZ) * 4)   // 75776 bytes

template<bool SPLIT, bool ROUND_OUT>
__global__ void __launch_bounds__(256, 2) gemm_ca(
    const float* __restrict__ X0, const float* __restrict__ W0,
    const float* __restrict__ b0, float* __restrict__ o0,
    const float* __restrict__ X1, const float* __restrict__ W1,
    const float* __restrict__ b1, float* __restrict__ o1,
    const float* __restrict__ X2, const float* __restrict__ W2,
    const float* __restrict__ b2, float* __restrict__ o2)
{
    const float* X = X0; const float* W = W0; const float* bias = b0; float* out = o0;
    if (blockIdx.z == 1) { X = X1; W = W1; bias = b1; out = o1; }
    else if (blockIdx.z == 2) { X = X2; W = W2; bias = b2; out = o2; }

    extern __shared__ float smb[];
    float* Asm[2] = { smb,             smb + ASZ };
    float* Bsm[2] = { smb + 2 * ASZ,   smb + 2 * ASZ + BSZ };
    float* Cs = smb;                    // alias for epilogue (per-warp 16x16)

    int tid = threadIdx.x;
    int w = tid >> 5, lane = tid & 31;
    int bm = blockIdx.y * 128, bn = blockIdx.x * 128;
    int wm = (w >> 1) * 32;
    int wn = (w & 1) * 64;

    int ar[4], ac4 = (tid & 7) << 2;
    int br[4], bc4 = (tid & 31) << 2;
    #pragma unroll
    for (int i = 0; i < 4; i++) { ar[i] = (tid + i * 256) >> 3; br[i] = (tid + i * 256) >> 5; }

    wmma::fragment<wmma::accumulator, 16, 16, 8, float> acc[2][4];
    #pragma unroll
    for (int mt = 0; mt < 2; mt++)
        #pragma unroll
        for (int nt = 0; nt < 4; nt++) wmma::fill_fragment(acc[mt][nt], 0.f);

    // tile issue: A rows bm..bm+127 cols t*32.., B rows t*32.. cols bn..bn+127
    auto issue = [&](int t, int s) {
        #pragma unroll
        for (int i = 0; i < 4; i++) {
            cp16(&Asm[s][ar[i] * ALD + ac4], &X[(size_t)(bm + ar[i]) * Dn + t * 32 + ac4]);
            cp16(&Bsm[s][br[i] * BLD + bc4], &W[(size_t)(t * 32 + br[i]) * Dn + bn + bc4]);
        }
        cp_commit();
    };

    issue(0, 0);

    const int NT = Dn / 32;  // 32 k-tiles
    for (int t = 0; t < NT; t++) {
        int s = t & 1;
        cp_wait0();
        __syncthreads();
        if (t + 1 < NT) issue(t + 1, s ^ 1);

        #pragma unroll
        for (int kk = 0; kk < 32; kk += 8) {
            wmma::fragment<wmma::matrix_a, 16, 16, 8, wmma::precision::tf32, wmma::row_major> af[2];
            wmma::fragment<wmma::matrix_b, 16, 16, 8, wmma::precision::tf32, wmma::row_major> bf[4];
            #pragma unroll
            for (int mt = 0; mt < 2; mt++)
                wmma::load_matrix_sync(af[mt], &Asm[s][(wm + mt * 16) * ALD + kk], ALD);
            #pragma unroll
            for (int nt = 0; nt < 4; nt++)
                wmma::load_matrix_sync(bf[nt], &Bsm[s][kk * BLD + wn + nt * 16], BLD);
            #pragma unroll
            for (int mt = 0; mt < 2; mt++)
                #pragma unroll
                for (int nt = 0; nt < 4; nt++)
                    wmma::mma_sync(acc[mt][nt], af[mt], bf[nt], acc[mt][nt]);
        }
        __syncthreads();
    }

    // epilogue via per-warp smem patch (Cs aliases stage memory; all mma done)
    #pragma unroll
    for (int mt = 0; mt < 2; mt++) {
        #pragma unroll
        for (int nt = 0; nt < 4; nt++) {
            wmma::store_matrix_sync(&Cs[w * 256], acc[mt][nt], 16, wmma::mem_row_major);
            __syncwarp();
            int r = lane >> 1;
            int c = (lane & 1) * 8;
            int m = bm + wm + mt * 16 + r;
            int n0 = bn + wn + nt * 16 + c;
            #pragma unroll
            for (int jj = 0; jj < 8; jj += 4) {
                float4 v = *(float4*)&Cs[w * 256 + r * 16 + c + jj];
                float4 bb = *(const float4*)&bias[n0 + jj];
                v.x += bb.x; v.y += bb.y; v.z += bb.z; v.w += bb.w;
                if (ROUND_OUT) {
                    v.x = wmma::__float_to_tf32(v.x);
                    v.y = wmma::__float_to_tf32(v.y);
                    v.z = wmma::__float_to_tf32(v.z);
                    v.w = wmma::__float_to_tf32(v.w);
                }
                if (SPLIT) {
                    int n = n0 + jj;
                    int h = n >> 6, d = n & 63;
                    int b = m >> 11, s2 = m & (Sn - 1);
                    *(float4*)&out[(((size_t)(b * Hn + h)) * Sn + s2) * DPn + d] = v;
                } else {
                    *(float4*)&out[(size_t)m * Dn + n0 + jj] = v;
                }
            }
            __syncwarp();
        }
    }
}

// ---------------------------------------------------------------------------
// K1: scores = (Q*scale)@K^T, mask, softmax, write attn.
// g_q/g_k pre-rounded tf32 -> staging is raw float4 copies.
// ---------------------------------------------------------------------------
#define SLD 2056
#define KTR 256
#define KVLD 72

__global__ void __launch_bounds__(512) attn_scores(
    const float* __restrict__ Mask, float* __restrict__ attn_out)
{
    extern __shared__ float sm[];
    float* sQ  = sm;                   // 16 x 72
    float* sS  = sm + 16 * KVLD;       // 16 x 2056
    float* sKV = sS + 16 * SLD;        // 256 x 72

    int tid = threadIdx.x, w = tid >> 5, lane = tid & 31;
    int q0 = blockIdx.x * 16;
    int h = blockIdx.y, b = blockIdx.z;
    size_t hb = ((size_t)(b * Hn + h)) * Sn * DPn;

    if (tid < 256) {
        int r = tid >> 4, c4 = (tid & 15) << 2;
        float4 v = *(const float4*)&g_q[hb + (size_t)(q0 + r) * DPn + c4];
        // *0.125f is exact (exponent shift) -> stays tf32
        v.x *= 0.125f; v.y *= 0.125f; v.z *= 0.125f; v.w *= 0.125f;
        *(float4*)&sQ[r * KVLD + c4] = v;
    }
    __syncthreads();

    wmma::fragment<wmma::matrix_a, 16, 16, 8, wmma::precision::tf32, wmma::row_major> aq[8];
    #pragma unroll
    for (int kk = 0; kk < 8; kk++)
        wmma::load_matrix_sync(aq[kk], &sQ[kk * 8], KVLD);

    int srow = tid >> 4, sc4 = (tid & 15) << 2;

    float4 pf[8];
    #pragma unroll
    for (int i = 0; i < 8; i++)
        pf[i] = *(const float4*)&g_k[hb + (size_t)(srow + i * 32) * DPn + sc4];

    for (int t = 0; t < Sn / KTR; t++) {
        #pragma unroll
        for (int i = 0; i < 8; i++)
            *(float4*)&sKV[(srow + i * 32) * KVLD + sc4] = pf[i];
        __syncthreads();

        if (t + 1 < Sn / KTR) {
            size_t nb = hb + (size_t)(t + 1) * KTR * DPn;
            #pragma unroll
            for (int i = 0; i < 8; i++)
                pf[i] = *(const float4*)&g_k[nb + (size_t)(srow + i * 32) * DPn + sc4];
        }

        wmma::fragment<wmma::accumulator, 16, 16, 8, float> acc;
        wmma::fill_fragment(acc, 0.f);
        #pragma unroll
        for (int kk = 0; kk < 8; kk++) {
            wmma::fragment<wmma::matrix_b, 16, 16, 8, wmma::precision::tf32, wmma::col_major> bk;
            wmma::load_matrix_sync(bk, &sKV[(w * 16) * KVLD + kk * 8], KVLD);
            wmma::mma_sync(acc, aq[kk], bk, acc);
        }
        wmma::store_matrix_sync(&sS[t * KTR + w * 16], acc, SLD, wmma::mem_row_major);
        __syncthreads();
    }

    // softmax: one warp per row
    {
        int r = w;
        float* row = &sS[r * SLD];
        const float* mrow = &Mask[((size_t)b * Sn + (q0 + r)) * Sn];
        float mx = -3.4e38f;
        #pragma unroll 4
        for (int c = 0; c < 16; c++) {
            int jj = lane * 4 + c * 128;
            float4 s4 = *(float4*)&row[jj];
            float4 m4 = *(const float4*)&mrow[jj];
            s4.x += m4.x * (-1e9f); s4.y += m4.y * (-1e9f);
            s4.z += m4.z * (-1e9f); s4.w += m4.w * (-1e9f);
            *(float4*)&row[jj] = s4;
            mx = fmaxf(mx, fmaxf(fmaxf(s4.x, s4.y), fmaxf(s4.z, s4.w)));
        }
        #pragma unroll
        for (int o = 16; o; o >>= 1) mx = fmaxf(mx, __shfl_xor_sync(0xffffffffu, mx, o));
        float sum = 0.f;
        #pragma unroll 4
        for (int c = 0; c < 16; c++) {
            int jj = lane * 4 + c * 128;
            float4 s4 = *(float4*)&row[jj];
            s4.x = __expf(s4.x - mx); s4.y = __expf(s4.y - mx);
            s4.z = __expf(s4.z - mx); s4.w = __expf(s4.w - mx);
            *(float4*)&row[jj] = s4;
            sum += s4.x + s4.y + s4.z + s4.w;
        }
        #pragma unroll
        for (int o = 16; o; o >>= 1) sum += __shfl_xor_sync(0xffffffffu, sum, o);
        float inv = 1.f / sum;
        float* arow = &attn_out[(((size_t)(b * Hn + h)) * Sn + (q0 + r)) * Sn];
        #pragma unroll 4
        for (int c = 0; c < 16; c++) {
            int jj = lane * 4 + c * 128;
            float4 s4 = *(float4*)&row[jj];
            s4.x *= inv; s4.y *= inv; s4.z *= inv; s4.w *= inv;
            *(float4*)&arow[jj] = s4;
        }
    }
}

// ---------------------------------------------------------------------------
// K2: concat = P @ V. V pre-rounded (raw copy); P rounded at staging.
// Epilogue rounds result (feeds final GEMM A path).
// ---------------------------------------------------------------------------
__global__ void __launch_bounds__(256) attn_pv(const float* __restrict__ P)
{
    __shared__ float sP[128][40];
    __shared__ float sV[32][72];

    int tid = threadIdx.x, w = tid >> 5;
    int m0 = blockIdx.x * 128;
    int h = blockIdx.y, b = blockIdx.z;
    const float* Ph = P + ((size_t)(b * Hn + h)) * Sn * Sn;
    const float* Vh = g_v + ((size_t)(b * Hn + h)) * Sn * DPn;

    int pr[4], pc4 = (tid & 7) << 2;
    #pragma unroll
    for (int i = 0; i < 4; i++) pr[i] = (tid + i * 256) >> 3;
    int vr0 = tid >> 4, vr1 = (tid + 256) >> 4, vc4 = (tid & 15) << 2;

    wmma::fragment<wmma::accumulator, 16, 16, 8, float> acc[4];
    #pragma unroll
    for (int nt = 0; nt < 4; nt++) wmma::fill_fragment(acc[nt], 0.f);

    float4 pp[4], pv0, pv1;
    #pragma unroll
    for (int i = 0; i < 4; i++)
        pp[i] = *(const float4*)&Ph[(size_t)(m0 + pr[i]) * Sn + pc4];
    pv0 = *(const float4*)&Vh[(size_t)vr0 * DPn + vc4];
    pv1 = *(const float4*)&Vh[(size_t)vr1 * DPn + vc4];

    for (int k0 = 0; k0 < Sn; k0 += 32) {
        #pragma unroll
        for (int i = 0; i < 4; i++) {
            sP[pr[i]][pc4+0] = wmma::__float_to_tf32(pp[i].x);
            sP[pr[i]][pc4+1] = wmma::__float_to_tf32(pp[i].y);
            sP[pr[i]][pc4+2] = wmma::__float_to_tf32(pp[i].z);
            sP[pr[i]][pc4+3] = wmma::__float_to_tf32(pp[i].w);
        }
        *(float4*)&sV[vr0][vc4] = pv0;
        *(float4*)&sV[vr1][vc4] = pv1;
        __syncthreads();

        if (k0 + 32 < Sn) {
            int kn = k0 + 32;
            #pragma unroll
            for (int i = 0; i < 4; i++)
                pp[i] = *(const float4*)&Ph[(size_t)(m0 + pr[i]) * Sn + kn + pc4];
            pv0 = *(const float4*)&Vh[(size_t)(kn + vr0) * DPn + vc4];
            pv1 = *(const float4*)&Vh[(size_t)(kn + vr1) * DPn + vc4];
        }

        #pragma unroll
        for (int kk = 0; kk < 32; kk += 8) {
            wmma::fragment<wmma::matrix_a, 16, 16, 8, wmma::precision::tf32, wmma::row_major> ap;
            wmma::load_matrix_sync(ap, &sP[w * 16][kk], 40);
            #pragma unroll
            for (int nt = 0; nt < 4; nt++) {
                wmma::fragment<wmma::matrix_b, 16, 16, 8, wmma::precision::tf32, wmma::row_major> bv;
                wmma::load_matrix_sync(bv, &sV[kk][nt * 16], 72);
                wmma::mma_sync(acc[nt], ap, bv, acc[nt]);
            }
        }
        __syncthreads();
    }

    #pragma unroll
    for (int nt = 0; nt < 4; nt++) {
        #pragma unroll
        for (int i = 0; i < acc[nt].num_elements; i++)
            acc[nt].x[i] = wmma::__float_to_tf32(acc[nt].x[i]);
        float* dst = &g_concat[((size_t)b * Sn + (m0 + w * 16)) * Dn + h * DPn + nt * 16];
        wmma::store_matrix_sync(dst, acc[nt], Dn, wmma::mem_row_major);
    }
}

// ---------------------------------------------------------------------------
// Launch
// ---------------------------------------------------------------------------
extern "C" void kernel_launch(void* const* d_in, const int* in_sizes, int n_in,
                              void* d_out, int out_size)
{
    const float* Q    = (const float*)d_in[0];
    const float* K    = (const float*)d_in[1];
    const float* V    = (const float*)d_in[2];
    const float* Mask = (const float*)d_in[3];
    const float* Wq   = (const float*)d_in[4];
    const float* bq   = (const float*)d_in[5];
    const float* Wk   = (const float*)d_in[6];
    const float* bk   = (const float*)d_in[7];
    const float* Wv   = (const float*)d_in[8];
    const float* bv   = (const float*)d_in[9];
    const float* Wo   = (const float*)d_in[10];
    const float* bo   = (const float*)d_in[11];

    float *qp, *kp, *vp, *cp, *fb, *afb, *rx, *rw;
    cudaGetSymbolAddress((void**)&qp, g_q);
    cudaGetSymbolAddress((void**)&kp, g_k);
    cudaGetSymbolAddress((void**)&vp, g_v);
    cudaGetSymbolAddress((void**)&cp, g_concat);
    cudaGetSymbolAddress((void**)&fb, g_out_fallback);
    cudaGetSymbolAddress((void**)&afb, g_attn_fb);
    cudaGetSymbolAddress((void**)&rx, g_rx);
    cudaGetSymbolAddress((void**)&rw, g_rw);

    float* rX[3] = { rx, rx + (size_t)Mn*Dn, rx + 2*(size_t)Mn*Dn };
    float* rW[4] = { rw, rw + (size_t)Dn*Dn, rw + 2*(size_t)Dn*Dn, rw + 3*(size_t)Dn*Dn };

    const long long OUT_N  = (long long)Bn * Sn * Dn;
    const long long ATTN_N = (long long)Bn * Hn * Sn * Sn;
    float* outp  = (float*)d_out;
    float* attnp = afb;
    long long osz = (long long)out_size;
    if (osz >= OUT_N + ATTN_N) {
        attnp = (float*)d_out + OUT_N;
    } else if (osz == ATTN_N) {
        attnp = (float*)d_out;
        outp  = fb;
    }

    // Pre-round inputs + weights to tf32
    RoundArgs ra;
    ra.s[0] = Q;  ra.d[0] = rX[0]; ra.n[0] = Mn * Dn;
    ra.s[1] = K;  ra.d[1] = rX[1]; ra.n[1] = Mn * Dn;
    ra.s[2] = V;  ra.d[2] = rX[2]; ra.n[2] = Mn * Dn;
    ra.s[3] = Wq; ra.d[3] = rW[0]; ra.n[3] = Dn * Dn;
    ra.s[4] = Wk; ra.d[4] = rW[1]; ra.n[4] = Dn * Dn;
    ra.s[5] = Wv; ra.d[5] = rW[2]; ra.n[5] = Dn * Dn;
    ra.s[6] = Wo; ra.d[6] = rW[3]; ra.n[6] = Dn * Dn;
    round_tf32_k<<<dim3((Mn * Dn / 4 + 255) / 256, 7), 256>>>(ra);

    // QKV projections (outputs tf32-rounded, head-split)
    cudaFuncSetAttribute(gemm_ca<true, true>,  cudaFuncAttributeMaxDynamicSharedMemorySize, GSM);
    cudaFuncSetAttribute(gemm_ca<false, false>, cudaFuncAttributeMaxDynamicSharedMemorySize, GSM);

    dim3 ggrid(Dn / 128, Mn / 128, 3);
    gemm_ca<true, true><<<ggrid, 256, GSM>>>(rX[0], rW[0], bq, qp,
                                             rX[1], rW[1], bk, kp,
                                             rX[2], rW[2], bv, vp);

    size_t shmem = (size_t)(16 * KVLD + 16 * SLD + KTR * KVLD) * sizeof(float);
    cudaFuncSetAttribute(attn_scores, cudaFuncAttributeMaxDynamicSharedMemorySize, (int)shmem);
    attn_scores<<<dim3(Sn / 16, Hn, Bn), 512, shmem>>>(Mask, attnp);

    attn_pv<<<dim3(Sn / 128, Hn, Bn), 256>>>(attnp);

    dim3 ogrid(Dn / 128, Mn / 128, 1);
    gemm_ca<false, false><<<ogrid, 256, GSM>>>(cp, rW[3], bo, outp,
                                               cp, rW[3], bo, outp,
                                               cp, rW[3], bo, outp);
}